// round 10
// baseline (speedup 1.0000x reference)
#include <cuda_runtime.h>
#include <cuda_bf16.h>
#include <math.h>

// ---------------- Problem constants ----------------
#define BATCH 32
#define CIN   64
#define HIN   64
#define WIN   64
#define KOUT  128
#define OHH   62
#define OWW   62
#define LOC   3844            // OHH*OWW
#define BL    123008          // BATCH*LOC
#define RDIM  576             // CIN*3*3
#define HW    4096            // HIN*WIN
#define Y_ELEMS 15745024      // BATCH*KOUT*LOC

typedef unsigned long long u64;
typedef unsigned int u32;

// ---------------- Precomputed operands (module globals) ----------------
#define XSPLIT (32 * 64 * 66 * 64)              // halves per split
__device__ __align__(16) unsigned short g_xs[2 * XSPLIT];   // ~34.6MB
__device__ __align__(16) unsigned short g_ws[9 * 2 * KOUT * CIN];
__device__ float g_wT[RDIM * KOUT];   // normalized fp32 weights, [r][k] (refine path)

__device__ float g_winv[KOUT];
__device__ int   g_winner[BL];
__device__ int   g_counts[KOUT];
__device__ int   g_offsets[KOUT + 1];
__device__ int   g_cursor[KOUT];
__device__ int   g_list[BL];
__device__ int   g_nrefine;
__device__ int   g_refine[BL];

#define RTHRESH 0.005f        // near-tie gap threshold (~100x max y abs error)

// ---------------- PTX helpers (all sm_80-level; compile for plain sm_100) ----------------
__device__ __forceinline__ u32 smem_u32(const void* p) {
    u32 a;
    asm("{ .reg .u64 t; cvta.to.shared.u64 t, %1; cvt.u32.u64 %0, t; }" : "=r"(a) : "l"(p));
    return a;
}
__device__ __forceinline__ void cpa16(u32 dst, const void* src) {
    asm volatile("cp.async.cg.shared.global [%0], [%1], 16;" :: "r"(dst), "l"(src));
}
#define CP_COMMIT() asm volatile("cp.async.commit_group;" ::: "memory")
#define CP_WAIT0()  asm volatile("cp.async.wait_group 0;" ::: "memory")

__device__ __forceinline__ void ldmx4(u32* r, u32 addr) {
    asm volatile("ldmatrix.sync.aligned.m8n8.x4.shared.b16 {%0,%1,%2,%3}, [%4];"
                 : "=r"(r[0]), "=r"(r[1]), "=r"(r[2]), "=r"(r[3]) : "r"(addr));
}
__device__ __forceinline__ void ldmx2(u32* r, u32 addr) {
    asm volatile("ldmatrix.sync.aligned.m8n8.x2.shared.b16 {%0,%1}, [%2];"
                 : "=r"(r[0]), "=r"(r[1]) : "r"(addr));
}
// D(16x8,f32) += A(16x16,bf16 row) * B(16x8,bf16 col)
__device__ __forceinline__ void mma16816(float* d, const u32* a, const u32* b) {
    asm volatile("mma.sync.aligned.m16n8k16.row.col.f32.bf16.bf16.f32 "
                 "{%0,%1,%2,%3}, {%4,%5,%6,%7}, {%8,%9}, {%0,%1,%2,%3};"
                 : "+f"(d[0]), "+f"(d[1]), "+f"(d[2]), "+f"(d[3])
                 : "r"(a[0]), "r"(a[1]), "r"(a[2]), "r"(a[3]), "r"(b[0]), "r"(b[1]));
}
// sortable pack: bigger value wins; ties -> smaller k wins
__device__ __forceinline__ u64 pack_vk(float v, int k) {
    u32 s = __float_as_uint(v);
    s = (s & 0x80000000u) ? ~s : (s | 0x80000000u);
    return ((u64)s << 32) | (u32)(127 - k);
}
__device__ __forceinline__ float unpack_v(u64 p) {
    u32 s = (u32)(p >> 32);
    u32 bits = (s & 0x80000000u) ? (s ^ 0x80000000u) : ~s;
    return __uint_as_float(bits);
}

// ---------------- 1) weight inverse norms + zero counters ----------------
__global__ void norm_kernel(const float* __restrict__ w) {
    int k = blockIdx.x;
    int tid = threadIdx.x;
    __shared__ float red[256];
    float s = 0.f;
    for (int t = tid; t < RDIM; t += 256) { float v = w[k * RDIM + t]; s += v * v; }
    red[tid] = s;
    __syncthreads();
    for (int off = 128; off > 0; off >>= 1) {
        if (tid < off) red[tid] += red[tid + off];
        __syncthreads();
    }
    if (tid == 0) {
        float n = sqrtf(red[0]);
        g_winv[k] = (n == 0.f) ? 1.f : (1.f / n);
    }
    if (blockIdx.x == 0 && tid < KOUT) g_counts[tid] = 0;
    if (blockIdx.x == 0 && tid == 0) g_nrefine = 0;
}

// ---------------- 2) build split weight operands + fp32 wT + zero wu ----------------
__global__ void wbuild_kernel(const float* __restrict__ w, float* __restrict__ wu) {
    int bx = blockIdx.x, tid = threadIdx.x;
    if (bx < 18) {
        int tap = bx >> 1, s = bx & 1;
        int i = tap / 3, j = tap % 3;
        for (int e = tid; e < KOUT * CIN; e += 256) {
            int n = e >> 6, c = e & 63;
            float wn = w[((n * 64 + c) * 3 + i) * 3 + j] * g_winv[n];
            __nv_bfloat16 hb = __float2bfloat16(wn);
            __nv_bfloat16 out = (s == 0) ? hb : __float2bfloat16(wn - __bfloat162float(hb));
            g_ws[((tap * 2 + s) * KOUT + n) * CIN + c] = __bfloat16_as_ushort(out);
            if (s == 0) g_wT[(c * 9 + tap) * KOUT + n] = wn;   // [r][k] for refine
        }
    } else {
        for (int idx = (bx - 18) * 256 + tid; idx < KOUT * RDIM; idx += 32 * 256)
            wu[idx] = 0.f;
    }
}

// ---------------- 3) build transposed/split X operand ----------------
__global__ void xbuild_kernel(const float* __restrict__ x) {
    __shared__ float plane[64 * 65];
    int bh = blockIdx.x;                    // b*64 + h
    int b = bh >> 6, h = bh & 63;
    int tid = threadIdx.x;
    for (int idx = tid; idx < 4096; idx += 256) {
        int c = idx >> 6, ww = idx & 63;
        plane[c * 65 + ww] = x[((size_t)(b * 64 + c) * 64 + h) * 64 + ww];
    }
    __syncthreads();
    size_t rowbase = (size_t)bh * 66 * 64;
    for (int idx = tid; idx < 66 * 64; idx += 256) {
        int ww = idx >> 6, c = idx & 63;
        float v = (ww < 64) ? plane[c * 65 + ww] : 0.f;
        __nv_bfloat16 hb = __float2bfloat16(v);
        __nv_bfloat16 lb = __float2bfloat16(v - __bfloat162float(hb));
        g_xs[rowbase + (size_t)ww * 64 + c]          = __bfloat16_as_ushort(hb);
        g_xs[XSPLIT + rowbase + (size_t)ww * 64 + c] = __bfloat16_as_ushort(lb);
    }
}

// ---------------- 4) HMMA conv + fused argmax/near-tie/count ----------------
// CTA (ohp, b): M=128 k x N=128 locs (2 oh x 64 ww), K=64/tap.
// 8 warps = 4m x 2n; warp tile m32 x n64.
#define SX_ROWS 264                 // 4 h-rows x 66 w
#define ROWH 72                     // smem row = 144B (conflict-free ldmatrix)
#define SW_BYTE_OFF (2 * SX_ROWS * ROWH * 2)        // 76032
#define SMEM_BYTES (SW_BYTE_OFF + 2 * 2 * KOUT * ROWH * 2)  // 149760

__global__ __launch_bounds__(256, 1)
void conv_mma_kernel(const float* __restrict__ bias, float* __restrict__ y) {
    extern __shared__ __align__(16) unsigned short sm[];
    u32 smb = smem_u32(sm);
    int tid = threadIdx.x;
    int warp = tid >> 5, lane = tid & 31;
    int wm = warp >> 1, wn = warp & 1;
    int m0 = wm * 32;
    int ohp = blockIdx.x, b = blockIdx.y;
    int oh0 = ohp * 2;
    int lane16 = lane & 15;

    // ---- stage X (both splits) + W tap0 into buf0 ----
    {
        size_t xg = ((size_t)(b * 64 + oh0) * 66) * 128;   // bytes into a split
        const char* x0 = (const char*)g_xs + xg;
        const char* x1 = (const char*)g_xs + (size_t)XSPLIT * 2 + xg;
        for (int i = tid; i < SX_ROWS * 8; i += 256) {      // 2112 chunks per split
            u32 d0 = smb + (i >> 3) * 144 + (i & 7) * 16;
            cpa16(d0, x0 + (size_t)i * 16);
            cpa16(d0 + SX_ROWS * 144, x1 + (size_t)i * 16);
        }
        const char* wsrc = (const char*)g_ws;               // tap 0
        for (int i = tid; i < 2048; i += 256) {
            cpa16(smb + SW_BYTE_OFF + (i >> 3) * 144 + (i & 7) * 16, wsrc + i * 16);
        }
        CP_COMMIT();
        CP_WAIT0();
        __syncthreads();
    }

    float acc[2][8][4];
#pragma unroll
    for (int mi = 0; mi < 2; mi++)
#pragma unroll
        for (int f = 0; f < 8; f++)
#pragma unroll
            for (int e = 0; e < 4; e++) acc[mi][f][e] = 0.f;

    for (int t = 0; t < 9; t++) {
        int buf = t & 1;
        if (t < 8) {                                        // prefetch next tap
            const char* wsrc = (const char*)g_ws + (size_t)(t + 1) * 32768;
            u32 dbase = smb + SW_BYTE_OFF + (buf ^ 1) * (256 * 144);
            for (int i = tid; i < 2048; i += 256)
                cpa16(dbase + (i >> 3) * 144 + (i & 7) * 16, wsrc + i * 16);
            CP_COMMIT();
        }

        int i_t = t / 3, j_t = t % 3;
        // A: row-major W[n][c], row = m0 + 16*mi + lane%16, col16 = lane/16
        u32 ab = smb + SW_BYTE_OFF + (buf * 256) * 144 + (m0 + (lane & 15)) * 144 + (lane >> 4) * 16;
        // B: rows = (wn+i)*66 + (8f + lane16%8 + j), col16 = lane16/8
        u32 bb = smb + ((wn + i_t) * 66 + j_t + (lane16 & 7)) * 144 + (lane16 >> 3) * 16;

#pragma unroll
        for (int k16 = 0; k16 < 4; k16++) {
            u32 col = k16 * 32;
            u32 ah[2][4], al[2][4];
            ldmx4(ah[0], ab + col);                       // s=0 (hi), mi=0
            ldmx4(ah[1], ab + 16 * 144 + col);            // s=0, mi=1
            ldmx4(al[0], ab + 128 * 144 + col);           // s=1 (lo), mi=0
            ldmx4(al[1], ab + 144 * 144 + col);           // s=1, mi=1
#pragma unroll
            for (int f = 0; f < 8; f++) {
                u32 bh[2], bl[2];
                ldmx2(bh, bb + f * 8 * 144 + col);                       // xh
                ldmx2(bl, bb + SX_ROWS * 144 + f * 8 * 144 + col);       // xl
                mma16816(acc[0][f], ah[0], bh);
                mma16816(acc[0][f], al[0], bh);
                mma16816(acc[0][f], ah[0], bl);
                mma16816(acc[1][f], ah[1], bh);
                mma16816(acc[1][f], al[1], bh);
                mma16816(acc[1][f], ah[1], bl);
            }
        }

        if (t < 8) CP_WAIT0();
        __syncthreads();
    }

    // ---- epilogue: reuse smem for fused argmax ----
    char* smc = (char*)sm;
    u64* smax = (u64*)smc;              // 128 * 8B
    int* sflag = (int*)(smc + 1024);    // 128 * 4B
    int* scnt  = (int*)(smc + 1536);    // 128 * 4B
    if (tid < 128) { smax[tid] = 0; sflag[tid] = 0; scnt[tid] = 0; }
    __syncthreads();

    int g = lane >> 2, tg = lane & 3;
    int oh = oh0 + wn;                                     // always < 62
    float bva = bias[m0 + g],      bvb = bias[m0 + 8 + g];
    float bvc = bias[m0 + 16 + g], bvd = bias[m0 + 24 + g];

    // y stores
#pragma unroll
    for (int mi = 0; mi < 2; mi++) {
        int k0 = m0 + 16 * mi + g;
        float bv0 = mi ? bvc : bva, bv1 = mi ? bvd : bvb;
        float* base0 = y + (size_t)(b * KOUT + k0) * LOC + oh * OWW;
#pragma unroll
        for (int f = 0; f < 8; f++) {
            int ww = f * 8 + tg * 2;
            if (ww <= 60) {
                float2 v0 = make_float2(acc[mi][f][0] + bv0, acc[mi][f][1] + bv0);
                float2 v1 = make_float2(acc[mi][f][2] + bv1, acc[mi][f][3] + bv1);
                *(float2*)(base0 + ww) = v0;
                *(float2*)(base0 + (size_t)8 * LOC + ww) = v1;
            }
        }
    }

    // per-location candidates -> packed atomicMax
#pragma unroll
    for (int f = 0; f < 8; f++)
#pragma unroll
        for (int e = 0; e < 2; e++) {
            int ww = f * 8 + tg * 2 + e;
            if (ww < OWW) {
                float v0 = acc[0][f][e]     + bva;
                float v1 = acc[0][f][e + 2] + bvb;
                float v2 = acc[1][f][e]     + bvc;
                float v3 = acc[1][f][e + 2] + bvd;
                float bv = v0; int bk = m0 + g;
                if (v1 > bv) { bv = v1; bk = m0 + 8 + g; }
                if (v2 > bv) { bv = v2; bk = m0 + 16 + g; }
                if (v3 > bv) { bv = v3; bk = m0 + 24 + g; }
                atomicMax(&smax[wn * 64 + ww], pack_vk(bv, bk));
            }
        }
    __syncthreads();

    // near-tie flags (complete: every k value is checked by its owner thread)
#pragma unroll
    for (int f = 0; f < 8; f++)
#pragma unroll
        for (int e = 0; e < 2; e++) {
            int ww = f * 8 + tg * 2 + e;
            if (ww < OWW) {
                u64 p = smax[wn * 64 + ww];
                int bk = 127 - (int)(p & 0xFFFFFFFFull);
                float bestv = unpack_v(p);
                float v0 = acc[0][f][e]     + bva;
                float v1 = acc[0][f][e + 2] + bvb;
                float v2 = acc[1][f][e]     + bvc;
                float v3 = acc[1][f][e + 2] + bvd;
                bool nt = (bk != m0 + g      && bestv - v0 < RTHRESH) ||
                          (bk != m0 + 8 + g  && bestv - v1 < RTHRESH) ||
                          (bk != m0 + 16 + g && bestv - v2 < RTHRESH) ||
                          (bk != m0 + 24 + g && bestv - v3 < RTHRESH);
                if (nt) sflag[wn * 64 + ww] = 1;
            }
        }
    __syncthreads();

    // winner write + counts + refine push
    if (tid < 128) {
        int ww = tid & 63, ohr = tid >> 6;
        if (ww < OWW) {
            u64 p = smax[tid];
            int bk = 127 - (int)(p & 0xFFFFFFFFull);
            int gloc = b * LOC + (oh0 + ohr) * OWW + ww;
            g_winner[gloc] = bk;
            atomicAdd(&scnt[bk], 1);
            if (sflag[tid]) {
                int ix = atomicAdd(&g_nrefine, 1);
                g_refine[ix] = gloc;
            }
        }
    }
    __syncthreads();
    if (tid < 128 && scnt[tid]) atomicAdd(&g_counts[tid], scnt[tid]);
}

// ---------------- 5) exact fp32 rescue of near-tie winners ----------------
__global__ __launch_bounds__(128)
void refine_kernel(const float* __restrict__ x) {
    __shared__ float patch[RDIM][16];
    __shared__ int soff[16];
    __shared__ float rv[128];
    __shared__ int rk[128];
    int tid = threadIdx.x;
    int n = g_nrefine;

    for (int base = blockIdx.x * 16; base < n; base += gridDim.x * 16) {
        int cnt = min(16, n - base);
        if (tid < 16) {
            int off = -1;
            if (tid < cnt) {
                int gloc = g_refine[base + tid];
                int b = gloc / LOC;
                int il = gloc - b * LOC;
                int oh = il / OWW, ow = il - oh * OWW;
                off = b * (CIN * HW) + oh * WIN + ow;
            }
            soff[tid] = off;
        }
        __syncthreads();
        for (int e = tid; e < RDIM * 16; e += 128) {
            int r = e >> 4, p = e & 15;
            int off = soff[p];
            float v = 0.f;
            if (off >= 0) {
                int c = r / 9, rem = r % 9;
                v = x[off + c * HW + (rem / 3) * WIN + (rem % 3)];
            }
            patch[r][p] = v;
        }
        __syncthreads();
        float acc[16];
#pragma unroll
        for (int p = 0; p < 16; p++) acc[p] = 0.f;
        for (int r = 0; r < RDIM; r++) {
            float wv = g_wT[r * KOUT + tid];           // coalesced
            const float4* pr = (const float4*)&patch[r][0];
            float4 p0 = pr[0], p1 = pr[1], p2 = pr[2], p3 = pr[3];
            acc[0]  += wv * p0.x;  acc[1]  += wv * p0.y;  acc[2]  += wv * p0.z;  acc[3]  += wv * p0.w;
            acc[4]  += wv * p1.x;  acc[5]  += wv * p1.y;  acc[6]  += wv * p1.z;  acc[7]  += wv * p1.w;
            acc[8]  += wv * p2.x;  acc[9]  += wv * p2.y;  acc[10] += wv * p2.z;  acc[11] += wv * p2.w;
            acc[12] += wv * p3.x;  acc[13] += wv * p3.y;  acc[14] += wv * p3.z;  acc[15] += wv * p3.w;
        }
        for (int p = 0; p < cnt; p++) {
            rv[tid] = acc[p];
            rk[tid] = tid;
            __syncthreads();
            for (int off = 64; off > 0; off >>= 1) {
                if (tid < off) {
                    float v2 = rv[tid + off];
                    int k2 = rk[tid + off];
                    if (v2 > rv[tid] || (v2 == rv[tid] && k2 < rk[tid])) {
                        rv[tid] = v2; rk[tid] = k2;
                    }
                }
                __syncthreads();
            }
            if (tid == 0) g_winner[g_refine[base + p]] = rk[0];
            __syncthreads();
        }
        __syncthreads();
    }
}

// ---------------- 6) exclusive scan of counts ----------------
__global__ void scan_kernel() {
    int t = threadIdx.x;               // 128
    int lane = t & 31, w = t >> 5;
    int v = g_counts[t];
    int inc = v;
#pragma unroll
    for (int o = 1; o < 32; o <<= 1) {
        int n = __shfl_up_sync(0xffffffffu, inc, o);
        if (lane >= o) inc += n;
    }
    __shared__ int wsum[4];
    if (lane == 31) wsum[w] = inc;
    __syncthreads();
    int add = 0;
#pragma unroll
    for (int i = 0; i < 4; i++) if (i < w) add += wsum[i];
    int excl = inc - v + add;
    g_offsets[t] = excl;
    g_cursor[t] = excl;
    if (t == 127) g_offsets[KOUT] = excl + v;
}

// NOTE: counts reflect PRE-refine winners; refine flips change per-k counts!
// Fix: count AFTER refine. scan reads g_counts built by count pass below.
// (count folded into conv used pre-refine winners -> rebuild counts here.)
__global__ void recount_kernel() {
    __shared__ int sc[KOUT];
    int t = threadIdx.x;
    sc[t] = 0;
    __syncthreads();
    atomicAdd(&sc[g_winner[blockIdx.x * 128 + t]], 1);
    __syncthreads();
    if (sc[t]) atomicAdd(&g_counts[t], sc[t]);
}
__global__ void zcnt_kernel() { g_counts[threadIdx.x] = 0; }

// ---------------- 7) scatter locations into per-k lists ----------------
__global__ void scatter_kernel() {
    int gloc = blockIdx.x * 128 + threadIdx.x;
    int k = g_winner[gloc];
    unsigned m = __match_any_sync(0xffffffffu, k);
    int lane = threadIdx.x & 31;
    int leader = __ffs(m) - 1;
    int prefix = __popc(m & ((1u << lane) - 1u));
    int base = 0;
    if (lane == leader) base = atomicAdd(&g_cursor[k], __popc(m));
    base = __shfl_sync(0xffffffffu, base, leader);
    g_list[base + prefix] = gloc;
}

// ---------------- 8) Hebbian gather ----------------
#define NSPLIT 8
__global__ __launch_bounds__(192)
void hebb_kernel(const float* __restrict__ x, float* __restrict__ wu) {
    int k = blockIdx.y;
    int start = g_offsets[k], end = g_offsets[k + 1];
    int len = end - start;
    int s0 = start + (int)((long long)len * blockIdx.x / NSPLIT);
    int s1 = start + (int)((long long)len * (blockIdx.x + 1) / NSPLIT);
    int t = threadIdx.x;

    int off[3];
    float a[3] = {0.f, 0.f, 0.f};
#pragma unroll
    for (int q = 0; q < 3; q++) {
        int r = t + q * 192;
        int c = r / 9, rem = r % 9;
        off[q] = c * HW + (rem / 3) * WIN + (rem % 3);
    }

    if (s0 < s1) {
        int nextg = g_list[s0];
        for (int p = s0; p < s1; p++) {
            int gloc = nextg;
            if (p + 1 < s1) nextg = g_list[p + 1];
            int b = gloc / LOC;
            int il = gloc - b * LOC;
            int oh = il / OWW;
            int ow = il - oh * OWW;
            const float* px = x + (size_t)b * (CIN * HW) + oh * WIN + ow;
            a[0] += px[off[0]];
            a[1] += px[off[1]];
            a[2] += px[off[2]];
        }
    }

    const float scale = 1.0f / 123008.0f;
#pragma unroll
    for (int q = 0; q < 3; q++)
        atomicAdd(&wu[k * RDIM + t + q * 192], a[q] * scale);
}

// ---------------- launch ----------------
extern "C" void kernel_launch(void* const* d_in, const int* in_sizes, int n_in,
                              void* d_out, int out_size) {
    const float* x    = (const float*)d_in[0];   // [32,64,64,64]
    const float* w    = (const float*)d_in[1];   // [128,64,3,3]
    const float* bias = (const float*)d_in[2];   // [128]
    float* y  = (float*)d_out;                   // [32,128,62,62]
    float* wu = y + (size_t)Y_ELEMS;             // [128,64,3,3]

    cudaFuncSetAttribute(conv_mma_kernel, cudaFuncAttributeMaxDynamicSharedMemorySize, SMEM_BYTES);

    norm_kernel<<<KOUT, 256>>>(w);                              // 1
    wbuild_kernel<<<50, 256>>>(w, wu);                          // 2
    xbuild_kernel<<<2048, 256>>>(x);                            // 3
    conv_mma_kernel<<<dim3(31, 32), 256, SMEM_BYTES>>>(bias, y);// 4 <- profiled slot
    refine_kernel<<<128, 128>>>(x);                             // 5
    zcnt_kernel<<<1, KOUT>>>();                                 // 6 (counts must be post-refine)
    recount_kernel<<<BL / 128, 128>>>();                        // 7
    scan_kernel<<<1, 128>>>();                                  // 8
    scatter_kernel<<<BL / 128, 128>>>();                        // 9
    hebb_kernel<<<dim3(NSPLIT, KOUT), 192>>>(x, wu);            // 10
}

// round 11
// speedup vs baseline: 1.0508x; 1.0508x over previous
#include <cuda_runtime.h>
#include <cuda_bf16.h>
#include <math.h>

// ---------------- Problem constants ----------------
#define BATCH 32
#define CIN   64
#define HIN   64
#define WIN   64
#define KOUT  128
#define OHH   62
#define OWW   62
#define LOC   3844            // OHH*OWW
#define BL    123008          // BATCH*LOC
#define RDIM  576             // CIN*3*3
#define HW    4096            // HIN*WIN
#define Y_ELEMS 15745024      // BATCH*KOUT*LOC

typedef unsigned long long u64;
typedef unsigned int u32;

// ---------------- Precomputed operands (module globals) ----------------
#define XSPLIT (32 * 64 * 66 * 64)              // halves per split
__device__ __align__(16) unsigned short g_xs[2 * XSPLIT];   // ~34.6MB
__device__ __align__(16) unsigned short g_ws[9 * 2 * KOUT * CIN];
__device__ float g_wT[RDIM * KOUT];   // normalized fp32 weights, [r][k] (refine path)

__device__ float g_winv[KOUT];
__device__ int   g_winner[BL];
__device__ int   g_counts[KOUT];
__device__ int   g_offsets[KOUT + 1];
__device__ int   g_cursor[KOUT];
__device__ int   g_list[BL];
__device__ int   g_nrefine;
__device__ int   g_refine[BL];

#define RTHRESH 0.005f        // near-tie gap threshold (~100x max y abs error)

// ---------------- PTX helpers (all sm_80-level; compile for plain sm_100) ----------------
__device__ __forceinline__ u32 smem_u32(const void* p) {
    u32 a;
    asm("{ .reg .u64 t; cvta.to.shared.u64 t, %1; cvt.u32.u64 %0, t; }" : "=r"(a) : "l"(p));
    return a;
}
__device__ __forceinline__ void cpa16(u32 dst, const void* src) {
    asm volatile("cp.async.cg.shared.global [%0], [%1], 16;" :: "r"(dst), "l"(src));
}
#define CP_COMMIT() asm volatile("cp.async.commit_group;" ::: "memory")
#define CP_WAIT0()  asm volatile("cp.async.wait_group 0;" ::: "memory")

__device__ __forceinline__ void ldmx4(u32* r, u32 addr) {
    asm volatile("ldmatrix.sync.aligned.m8n8.x4.shared.b16 {%0,%1,%2,%3}, [%4];"
                 : "=r"(r[0]), "=r"(r[1]), "=r"(r[2]), "=r"(r[3]) : "r"(addr));
}
// D(16x8,f32) += A(16x16,bf16 row) * B(16x8,bf16 col)
__device__ __forceinline__ void mma16816(float* d, const u32* a, const u32* b) {
    asm volatile("mma.sync.aligned.m16n8k16.row.col.f32.bf16.bf16.f32 "
                 "{%0,%1,%2,%3}, {%4,%5,%6,%7}, {%8,%9}, {%0,%1,%2,%3};"
                 : "+f"(d[0]), "+f"(d[1]), "+f"(d[2]), "+f"(d[3])
                 : "r"(a[0]), "r"(a[1]), "r"(a[2]), "r"(a[3]), "r"(b[0]), "r"(b[1]));
}

// ---------------- 1) weight inverse norms + zero counters ----------------
__global__ void norm_kernel(const float* __restrict__ w) {
    int k = blockIdx.x;
    int tid = threadIdx.x;
    __shared__ float red[256];
    float s = 0.f;
    for (int t = tid; t < RDIM; t += 256) { float v = w[k * RDIM + t]; s += v * v; }
    red[tid] = s;
    __syncthreads();
    for (int off = 128; off > 0; off >>= 1) {
        if (tid < off) red[tid] += red[tid + off];
        __syncthreads();
    }
    if (tid == 0) {
        float n = sqrtf(red[0]);
        g_winv[k] = (n == 0.f) ? 1.f : (1.f / n);
    }
    if (blockIdx.x == 0 && tid < KOUT) g_counts[tid] = 0;
    if (blockIdx.x == 0 && tid == 0) g_nrefine = 0;
}

// ---------------- 2) build split weight operands + fp32 wT + zero wu ----------------
__global__ void wbuild_kernel(const float* __restrict__ w, float* __restrict__ wu) {
    int bx = blockIdx.x, tid = threadIdx.x;
    if (bx < 18) {
        int tap = bx >> 1, s = bx & 1;
        int i = tap / 3, j = tap % 3;
        for (int e = tid; e < KOUT * CIN; e += 256) {
            int n = e >> 6, c = e & 63;
            float wn = w[((n * 64 + c) * 3 + i) * 3 + j] * g_winv[n];
            __nv_bfloat16 hb = __float2bfloat16(wn);
            __nv_bfloat16 out = (s == 0) ? hb : __float2bfloat16(wn - __bfloat162float(hb));
            g_ws[((tap * 2 + s) * KOUT + n) * CIN + c] = __bfloat16_as_ushort(out);
            if (s == 0) g_wT[(c * 9 + tap) * KOUT + n] = wn;   // [r][k] for refine
        }
    } else {
        for (int idx = (bx - 18) * 256 + tid; idx < KOUT * RDIM; idx += 32 * 256)
            wu[idx] = 0.f;
    }
}

// ---------------- 3) build transposed/split X operand ----------------
__global__ void xbuild_kernel(const float* __restrict__ x) {
    __shared__ float plane[64 * 65];
    int bh = blockIdx.x;                    // b*64 + h
    int b = bh >> 6, h = bh & 63;
    int tid = threadIdx.x;
    for (int idx = tid; idx < 4096; idx += 256) {
        int c = idx >> 6, ww = idx & 63;
        plane[c * 65 + ww] = x[((size_t)(b * 64 + c) * 64 + h) * 64 + ww];
    }
    __syncthreads();
    size_t rowbase = (size_t)bh * 66 * 64;
    for (int idx = tid; idx < 66 * 64; idx += 256) {
        int ww = idx >> 6, c = idx & 63;
        float v = (ww < 64) ? plane[c * 65 + ww] : 0.f;
        __nv_bfloat16 hb = __float2bfloat16(v);
        __nv_bfloat16 lb = __float2bfloat16(v - __bfloat162float(hb));
        g_xs[rowbase + (size_t)ww * 64 + c]          = __bfloat16_as_ushort(hb);
        g_xs[XSPLIT + rowbase + (size_t)ww * 64 + c] = __bfloat16_as_ushort(lb);
    }
}

// ---------------- 4) HMMA conv: 9 taps x 3 split products ----------------
// CTA (ohp, b): M=128 k x N=128 locs (2 oh x 64 ww), K=64/tap.
// 8 warps = 4m x 2n; warp tile m32 x n64.
#define SX_ROWS 264                 // 4 h-rows x 66 w
#define ROWH 72                     // smem row = 144B (conflict-free ldmatrix)
#define SW_BYTE_OFF (2 * SX_ROWS * ROWH * 2)        // 76032
#define SMEM_BYTES (SW_BYTE_OFF + 2 * 2 * KOUT * ROWH * 2)  // 149760

__global__ __launch_bounds__(256, 1)
void conv_mma_kernel(const float* __restrict__ bias, float* __restrict__ y) {
    extern __shared__ __align__(16) unsigned short sm[];
    u32 smb = smem_u32(sm);
    int tid = threadIdx.x;
    int warp = tid >> 5, lane = tid & 31;
    int wm = warp >> 1, wn = warp & 1;
    int m0 = wm * 32;
    int ohp = blockIdx.x, b = blockIdx.y;
    int oh0 = ohp * 2;

    // ---- stage X (both splits) + W tap0 into buf0 ----
    {
        size_t xg = ((size_t)(b * 64 + oh0) * 66) * 128;   // bytes into a split
        const char* x0 = (const char*)g_xs + xg;
        const char* x1 = (const char*)g_xs + (size_t)XSPLIT * 2 + xg;
        for (int i = tid; i < SX_ROWS * 8; i += 256) {      // 2112 chunks per split
            u32 d0 = smb + (i >> 3) * 144 + (i & 7) * 16;
            cpa16(d0, x0 + (size_t)i * 16);
            cpa16(d0 + SX_ROWS * 144, x1 + (size_t)i * 16);
        }
        const char* wsrc = (const char*)g_ws;               // tap 0
        for (int i = tid; i < 2048; i += 256) {
            cpa16(smb + SW_BYTE_OFF + (i >> 3) * 144 + (i & 7) * 16, wsrc + i * 16);
        }
        CP_COMMIT();
        CP_WAIT0();
        __syncthreads();
    }

    float acc[2][8][4];
#pragma unroll
    for (int mi = 0; mi < 2; mi++)
#pragma unroll
        for (int f = 0; f < 8; f++)
#pragma unroll
            for (int e = 0; e < 4; e++) acc[mi][f][e] = 0.f;

    for (int t = 0; t < 9; t++) {
        int buf = t & 1;
        if (t < 8) {                                        // prefetch next tap
            const char* wsrc = (const char*)g_ws + (size_t)(t + 1) * 32768;
            u32 dbase = smb + SW_BYTE_OFF + (buf ^ 1) * (256 * 144);
            for (int i = tid; i < 2048; i += 256)
                cpa16(dbase + (i >> 3) * 144 + (i & 7) * 16, wsrc + i * 16);
            CP_COMMIT();
        }

        int i_t = t / 3, j_t = t % 3;
        // A: row-major W[n][c], rows m0+(lane&15), col16 = lane>>4 (x4 layout)
        u32 ab = smb + SW_BYTE_OFF + (buf * 256) * 144 + (m0 + (lane & 15)) * 144 + (lane >> 4) * 16;
        // B x4 for an f-PAIR: lanes 0-15 -> rows of f, lanes 16-31 -> rows of f+1
        //   row = (wn+i)*66 + j + (lane&7) + (lane>=16 ? 8 : 0), col16 = (lane>>3)&1
        u32 bb4 = smb + (((wn + i_t) * 66 + j_t + (lane & 7) + ((lane >> 4) << 3)) * 144)
                + (((lane >> 3) & 1) << 4);

#pragma unroll
        for (int k16 = 0; k16 < 4; k16++) {
            u32 col = k16 * 32;
            u32 ah[2][4], al[2][4];
            ldmx4(ah[0], ab + col);                       // s=0 (hi), mi=0
            ldmx4(ah[1], ab + 16 * 144 + col);            // s=0, mi=1
            ldmx4(al[0], ab + 128 * 144 + col);           // s=1 (lo), mi=0
            ldmx4(al[1], ab + 144 * 144 + col);           // s=1, mi=1
#pragma unroll
            for (int fp = 0; fp < 4; fp++) {              // f pairs: f=2fp, 2fp+1
                u32 bh4[4], bl4[4];
                ldmx4(bh4, bb4 + fp * 16 * 144 + col);                    // xh, two f's
                ldmx4(bl4, bb4 + SX_ROWS * 144 + fp * 16 * 144 + col);    // xl, two f's
                int f0 = 2 * fp, f1 = 2 * fp + 1;
                mma16816(acc[0][f0], ah[0], bh4 + 0);
                mma16816(acc[0][f0], al[0], bh4 + 0);
                mma16816(acc[0][f0], ah[0], bl4 + 0);
                mma16816(acc[1][f0], ah[1], bh4 + 0);
                mma16816(acc[1][f0], al[1], bh4 + 0);
                mma16816(acc[1][f0], ah[1], bl4 + 0);
                mma16816(acc[0][f1], ah[0], bh4 + 2);
                mma16816(acc[0][f1], al[0], bh4 + 2);
                mma16816(acc[0][f1], ah[0], bl4 + 2);
                mma16816(acc[1][f1], ah[1], bh4 + 2);
                mma16816(acc[1][f1], al[1], bh4 + 2);
                mma16816(acc[1][f1], ah[1], bl4 + 2);
            }
        }

        if (t < 8) CP_WAIT0();
        __syncthreads();
    }

    // ---- epilogue: D fragments -> y (+bias), mask ww>=62 ----
    int g = lane >> 2, tg = lane & 3;
    int oh = oh0 + wn;                                     // always < 62
#pragma unroll
    for (int mi = 0; mi < 2; mi++) {
        int k0 = m0 + 16 * mi + g;
        float bv0 = bias[k0], bv1 = bias[k0 + 8];
        float* base0 = y + (size_t)(b * KOUT + k0) * LOC + oh * OWW;
#pragma unroll
        for (int f = 0; f < 8; f++) {
            int ww = f * 8 + tg * 2;
            if (ww <= 60) {
                float2 v0 = make_float2(acc[mi][f][0] + bv0, acc[mi][f][1] + bv0);
                float2 v1 = make_float2(acc[mi][f][2] + bv1, acc[mi][f][3] + bv1);
                *(float2*)(base0 + ww) = v0;
                *(float2*)(base0 + (size_t)8 * LOC + ww) = v1;
            }
        }
    }
}

// ---------------- 5) argmax + near-tie detection ----------------
__global__ void argmax_kernel(const float* __restrict__ y) {
    int gloc = blockIdx.x * 128 + threadIdx.x;     // 961*128 == BL exactly
    int b = gloc / LOC;
    int il = gloc - b * LOC;
    const float* yb = y + (size_t)b * KOUT * LOC + il;
    float best = yb[0], second = -3.4e38f;
    int bk = 0;
#pragma unroll 4
    for (int k = 1; k < KOUT; k++) {
        float v = yb[(size_t)k * LOC];
        if (v > best) { second = best; best = v; bk = k; }
        else if (v > second) { second = v; }
    }
    g_winner[gloc] = bk;
    if (best - second < RTHRESH) {
        int idx = atomicAdd(&g_nrefine, 1);
        g_refine[idx] = gloc;
    }
}

// ---------------- 6) exact fp32 rescue of near-tie winners ----------------
__global__ __launch_bounds__(128)
void refine_kernel(const float* __restrict__ x) {
    __shared__ float patch[RDIM][16];
    __shared__ int soff[16];
    __shared__ float rv[128];
    __shared__ int rk[128];
    int tid = threadIdx.x;
    int n = g_nrefine;

    for (int base = blockIdx.x * 16; base < n; base += gridDim.x * 16) {
        int cnt = min(16, n - base);
        if (tid < 16) {
            int off = -1;
            if (tid < cnt) {
                int gloc = g_refine[base + tid];
                int b = gloc / LOC;
                int il = gloc - b * LOC;
                int oh = il / OWW, ow = il - oh * OWW;
                off = b * (CIN * HW) + oh * WIN + ow;
            }
            soff[tid] = off;
        }
        __syncthreads();
        for (int e = tid; e < RDIM * 16; e += 128) {
            int r = e >> 4, p = e & 15;
            int off = soff[p];
            float v = 0.f;
            if (off >= 0) {
                int c = r / 9, rem = r % 9;
                v = x[off + c * HW + (rem / 3) * WIN + (rem % 3)];
            }
            patch[r][p] = v;
        }
        __syncthreads();
        float acc[16];
#pragma unroll
        for (int p = 0; p < 16; p++) acc[p] = 0.f;
        for (int r = 0; r < RDIM; r++) {
            float wv = g_wT[r * KOUT + tid];           // coalesced
            const float4* pr = (const float4*)&patch[r][0];
            float4 p0 = pr[0], p1 = pr[1], p2 = pr[2], p3 = pr[3];
            acc[0]  += wv * p0.x;  acc[1]  += wv * p0.y;  acc[2]  += wv * p0.z;  acc[3]  += wv * p0.w;
            acc[4]  += wv * p1.x;  acc[5]  += wv * p1.y;  acc[6]  += wv * p1.z;  acc[7]  += wv * p1.w;
            acc[8]  += wv * p2.x;  acc[9]  += wv * p2.y;  acc[10] += wv * p2.z;  acc[11] += wv * p2.w;
            acc[12] += wv * p3.x;  acc[13] += wv * p3.y;  acc[14] += wv * p3.z;  acc[15] += wv * p3.w;
        }
        for (int p = 0; p < cnt; p++) {
            rv[tid] = acc[p];
            rk[tid] = tid;
            __syncthreads();
            for (int off = 64; off > 0; off >>= 1) {
                if (tid < off) {
                    float v2 = rv[tid + off];
                    int k2 = rk[tid + off];
                    if (v2 > rv[tid] || (v2 == rv[tid] && k2 < rk[tid])) {
                        rv[tid] = v2; rk[tid] = k2;
                    }
                }
                __syncthreads();
            }
            if (tid == 0) g_winner[g_refine[base + p]] = rk[0];
            __syncthreads();
        }
        __syncthreads();
    }
}

// ---------------- 7) winner counts (post-refine) ----------------
__global__ void count_kernel() {
    __shared__ int sc[KOUT];
    int t = threadIdx.x;
    sc[t] = 0;
    __syncthreads();
    atomicAdd(&sc[g_winner[blockIdx.x * 128 + t]], 1);
    __syncthreads();
    if (sc[t]) atomicAdd(&g_counts[t], sc[t]);
}

// ---------------- 8) exclusive scan of counts ----------------
__global__ void scan_kernel() {
    int t = threadIdx.x;               // 128
    int lane = t & 31, w = t >> 5;
    int v = g_counts[t];
    int inc = v;
#pragma unroll
    for (int o = 1; o < 32; o <<= 1) {
        int n = __shfl_up_sync(0xffffffffu, inc, o);
        if (lane >= o) inc += n;
    }
    __shared__ int wsum[4];
    if (lane == 31) wsum[w] = inc;
    __syncthreads();
    int add = 0;
#pragma unroll
    for (int i = 0; i < 4; i++) if (i < w) add += wsum[i];
    int excl = inc - v + add;
    g_offsets[t] = excl;
    g_cursor[t] = excl;
    if (t == 127) g_offsets[KOUT] = excl + v;
}

// ---------------- 9) scatter locations into per-k lists ----------------
__global__ void scatter_kernel() {
    int gloc = blockIdx.x * 128 + threadIdx.x;
    int k = g_winner[gloc];
    unsigned m = __match_any_sync(0xffffffffu, k);
    int lane = threadIdx.x & 31;
    int leader = __ffs(m) - 1;
    int prefix = __popc(m & ((1u << lane) - 1u));
    int base = 0;
    if (lane == leader) base = atomicAdd(&g_cursor[k], __popc(m));
    base = __shfl_sync(0xffffffffu, base, leader);
    g_list[base + prefix] = gloc;
}

// ---------------- 10) Hebbian gather ----------------
#define NSPLIT 8
__global__ __launch_bounds__(192)
void hebb_kernel(const float* __restrict__ x, float* __restrict__ wu) {
    int k = blockIdx.y;
    int start = g_offsets[k], end = g_offsets[k + 1];
    int len = end - start;
    int s0 = start + (int)((long long)len * blockIdx.x / NSPLIT);
    int s1 = start + (int)((long long)len * (blockIdx.x + 1) / NSPLIT);
    int t = threadIdx.x;

    int off[3];
    float a[3] = {0.f, 0.f, 0.f};
#pragma unroll
    for (int q = 0; q < 3; q++) {
        int r = t + q * 192;
        int c = r / 9, rem = r % 9;
        off[q] = c * HW + (rem / 3) * WIN + (rem % 3);
    }

    if (s0 < s1) {
        int nextg = g_list[s0];
        for (int p = s0; p < s1; p++) {
            int gloc = nextg;
            if (p + 1 < s1) nextg = g_list[p + 1];
            int b = gloc / LOC;
            int il = gloc - b * LOC;
            int oh = il / OWW;
            int ow = il - oh * OWW;
            const float* px = x + (size_t)b * (CIN * HW) + oh * WIN + ow;
            a[0] += px[off[0]];
            a[1] += px[off[1]];
            a[2] += px[off[2]];
        }
    }

    const float scale = 1.0f / 123008.0f;
#pragma unroll
    for (int q = 0; q < 3; q++)
        atomicAdd(&wu[k * RDIM + t + q * 192], a[q] * scale);
}

// ---------------- launch ----------------
extern "C" void kernel_launch(void* const* d_in, const int* in_sizes, int n_in,
                              void* d_out, int out_size) {
    const float* x    = (const float*)d_in[0];   // [32,64,64,64]
    const float* w    = (const float*)d_in[1];   // [128,64,3,3]
    const float* bias = (const float*)d_in[2];   // [128]
    float* y  = (float*)d_out;                   // [32,128,62,62]
    float* wu = y + (size_t)Y_ELEMS;             // [128,64,3,3]

    cudaFuncSetAttribute(conv_mma_kernel, cudaFuncAttributeMaxDynamicSharedMemorySize, SMEM_BYTES);

    norm_kernel<<<KOUT, 256>>>(w);                              // 1
    wbuild_kernel<<<50, 256>>>(w, wu);                          // 2
    xbuild_kernel<<<2048, 256>>>(x);                            // 3
    conv_mma_kernel<<<dim3(31, 32), 256, SMEM_BYTES>>>(bias, y);// 4 <- profiled slot
    argmax_kernel<<<BL / 128, 128>>>(y);                        // 5
    refine_kernel<<<128, 128>>>(x);                             // 6
    count_kernel<<<BL / 128, 128>>>();                          // 7
    scan_kernel<<<1, 128>>>();                                  // 8
    scatter_kernel<<<BL / 128, 128>>>();                        // 9
    hebb_kernel<<<dim3(NSPLIT, KOUT), 192>>>(x, wu);            // 10
}